// round 10
// baseline (speedup 1.0000x reference)
#include <cuda_runtime.h>
#include <cuda_fp16.h>

#define NROWS 200000
#define NNZV  3200000
#define HID   128
#define HALF  64
#define NWARPS (NROWS / 2)   // two rows per warp

// ---------------- static device scratch (no runtime allocation) ----------------
__device__ int   g_cnt[NROWS];
__device__ int   g_rowptr[NROWS + 1];
__device__ int   g_cursor[NROWS];
__device__ int2  g_edge[NNZV];          // packed {col, val_bits}
__device__ float g_B0[NROWS * HID];
__device__ float g_B1[NROWS * HID];
__device__ float g_acc[NROWS * HID];
__device__ __half g_Ha[NROWS * HALF];   // fp16 mirror ping
__device__ __half g_Hb[NROWS * HALF];   // fp16 mirror pong
__device__ unsigned int g_maxbits[2][16];  // per-half per-step max|T_m| (float bits)
__device__ unsigned int g_sexp[2][16];     // scale exponent field used for T_m mirror
__device__ unsigned int g_maxx;            // max|x| bits
__device__ float g_w[20];
__device__ int   g_bsum[256];
__device__ int   g_is64;

// ---------------- cache-hint load/store helpers ----------------
__device__ __forceinline__ float4 ldcs4(const float4* p) {
    float4 r;
    asm volatile("ld.global.cs.v4.f32 {%0,%1,%2,%3}, [%4];"
                 : "=f"(r.x), "=f"(r.y), "=f"(r.z), "=f"(r.w) : "l"(p));
    return r;
}
__device__ __forceinline__ void stcs4(float4* p, float4 v) {
    asm volatile("st.global.cs.v4.f32 [%0], {%1,%2,%3,%4};"
                 :: "l"(p), "f"(v.x), "f"(v.y), "f"(v.z), "f"(v.w));
}

// ---------------- index dtype detection (int32 vs int64 edges) ----------------
__device__ __forceinline__ int edge_at(const void* p, int i) {
    return g_is64 ? (int)((const long long*)p)[i] : ((const int*)p)[i];
}

__global__ void detect_k(const unsigned int* p) {
    int t = threadIdx.x;
    if (t == 0) {
        int nz = 0;
        for (int i = 1; i < 128; i += 2) nz |= (p[i] != 0u);
        g_is64 = nz ? 0 : 1;
        g_maxx = 0u;
    }
    if (t < 32) {
        g_maxbits[0][t & 15] = 0u; g_maxbits[1][t & 15] = 0u;
        g_sexp[0][t & 15] = 0u;    g_sexp[1][t & 15] = 0u;
    }
}

// ---------------- max|x| over the whole feature matrix ----------------
__global__ void maxx_k(const float4* __restrict__ x) {
    int i = blockIdx.x * blockDim.x + threadIdx.x;
    float m = 0.f;
    int n4 = NROWS * HID / 4;
    for (; i < n4; i += gridDim.x * blockDim.x) {
        float4 a = __ldg(x + i);
        m = fmaxf(m, fmaxf(fmaxf(fabsf(a.x), fabsf(a.y)), fmaxf(fabsf(a.z), fabsf(a.w))));
    }
    #pragma unroll
    for (int d = 16; d > 0; d >>= 1)
        m = fmaxf(m, __shfl_xor_sync(0xffffffffu, m, d));
    if ((threadIdx.x & 31) == 0) atomicMax(&g_maxx, __float_as_uint(m));
}

// ---------------- CSR build: histogram -> scan -> scatter ----------------
__global__ void hist_k(const void* rowp) {
    int i = blockIdx.x * blockDim.x + threadIdx.x;
    if (i < NNZV) atomicAdd(&g_cnt[edge_at(rowp, i)], 1);
}

__global__ void scan_local_k() {
    int t = threadIdx.x;
    int base = blockIdx.x * 1024 + t * 4;
    int v0 = (base + 0 < NROWS) ? g_cnt[base + 0] : 0;
    int v1 = (base + 1 < NROWS) ? g_cnt[base + 1] : 0;
    int v2 = (base + 2 < NROWS) ? g_cnt[base + 2] : 0;
    int v3 = (base + 3 < NROWS) ? g_cnt[base + 3] : 0;
    int tsum = v0 + v1 + v2 + v3;
    int inc = tsum;
    #pragma unroll
    for (int d = 1; d < 32; d <<= 1) {
        int u = __shfl_up_sync(0xffffffffu, inc, d);
        if ((t & 31) >= d) inc += u;
    }
    __shared__ int wsum[8], woff[8];
    if ((t & 31) == 31) wsum[t >> 5] = inc;
    __syncthreads();
    if (t == 0) {
        int s = 0;
        for (int i = 0; i < 8; i++) { woff[i] = s; s += wsum[i]; }
        g_bsum[blockIdx.x] = s;
    }
    __syncthreads();
    int ex = inc - tsum + woff[t >> 5];
    if (base + 0 < NROWS) g_rowptr[base + 0] = ex;
    if (base + 1 < NROWS) g_rowptr[base + 1] = ex + v0;
    if (base + 2 < NROWS) g_rowptr[base + 2] = ex + v0 + v1;
    if (base + 3 < NROWS) g_rowptr[base + 3] = ex + v0 + v1 + v2;
}

__global__ void scan_bsum_k(int nb, const float* __restrict__ logits,
                            const float* __restrict__ alpha) {
    int t = threadIdx.x;
    int v = (t < nb) ? g_bsum[t] : 0;
    int inc = v;
    #pragma unroll
    for (int d = 1; d < 32; d <<= 1) {
        int u = __shfl_up_sync(0xffffffffu, inc, d);
        if ((t & 31) >= d) inc += u;
    }
    __shared__ int ws[8], wo[8];
    if ((t & 31) == 31) ws[t >> 5] = inc;
    __syncthreads();
    if (t == 0) {
        int s = 0;
        for (int i = 0; i < 8; i++) { wo[i] = s; s += ws[i]; }
    }
    __syncthreads();
    if (t < nb) g_bsum[t] = inc - v + wo[t >> 5];
    if (t == 224) {
        float m = logits[0];
        for (int i = 1; i < 16; i++) m = fmaxf(m, logits[i]);
        float e[16], s = 0.f;
        for (int i = 0; i < 16; i++) { e[i] = __expf(logits[i] - m); s += e[i]; }
        float inv = 1.f / s;
        for (int i = 0; i < 16; i++) g_w[i] = e[i] * inv;
        g_w[16] = *alpha;
    }
}

__global__ void scan_add_k() {
    int i = blockIdx.x * blockDim.x + threadIdx.x;
    if (i < NROWS) {
        int v = g_rowptr[i] + g_bsum[i >> 10];
        g_rowptr[i] = v;
        g_cursor[i] = v;
        if (i == 0) g_rowptr[NROWS] = NNZV;
    }
}

__global__ void scatter_k(const void* rowp, const void* colp, const float* __restrict__ v) {
    int i = blockIdx.x * blockDim.x + threadIdx.x;
    if (i < NNZV) {
        int r = edge_at(rowp, i);
        int p = atomicAdd(&g_cursor[r], 1);
        g_edge[p] = make_int2(edge_at(colp, i), __float_as_int(v[i]));
    }
}

// ---------------- gathers ----------------
__device__ __forceinline__ float4 spmm_half(const float* __restrict__ srcf, int hoff,
                                            int beg, int end, int lane16) {
    float4 s = make_float4(0.f, 0.f, 0.f, 0.f);
    #pragma unroll 4
    for (int j = beg; j < end; ++j) {
        int2 e = __ldg(g_edge + j);
        float v = __int_as_float(e.y);
        const float4* p = (const float4*)(srcf + e.x * HID + hoff) + lane16;
        float4 a = __ldg(p);
        s.x = fmaf(v, a.x, s.x); s.y = fmaf(v, a.y, s.y);
        s.z = fmaf(v, a.z, s.z); s.w = fmaf(v, a.w, s.w);
    }
    return s;
}

__device__ __forceinline__ float4 spmm_half_f16(const __half* __restrict__ H,
                                                int beg, int end, int lane16) {
    float4 s = make_float4(0.f, 0.f, 0.f, 0.f);
    #pragma unroll 4
    for (int j = beg; j < end; ++j) {
        int2 e = __ldg(g_edge + j);
        float v = __int_as_float(e.y);
        const uint2* p = (const uint2*)(H + (size_t)e.x * HALF) + lane16;
        uint2 u = __ldg(p);
        __half2 h01 = *(__half2*)&u.x;
        __half2 h23 = *(__half2*)&u.y;
        float2 f01 = __half22float2(h01);
        float2 f23 = __half22float2(h23);
        s.x = fmaf(v, f01.x, s.x); s.y = fmaf(v, f01.y, s.y);
        s.z = fmaf(v, f23.x, s.z); s.w = fmaf(v, f23.y, s.w);
    }
    return s;
}

__device__ __forceinline__ void tn_max_update(float4 tn, unsigned int* slot) {
    float m = fmaxf(fmaxf(fabsf(tn.x), fabsf(tn.y)), fmaxf(fabsf(tn.z), fabsf(tn.w)));
    #pragma unroll
    for (int d = 16; d > 0; d >>= 1)
        m = fmaxf(m, __shfl_xor_sync(0xffffffffu, m, d));
    if ((threadIdx.x & 31) == 0) atomicMax(slot, __float_as_uint(m));
}

__device__ __forceinline__ void mirror_write(__half* Hdst, size_t row, int lane16,
                                             float4 tn, unsigned int eS) {
    float inv = __uint_as_float((254u - eS) << 23);   // 2^(127-eS)
    __half2 h01 = __floats2half2_rn(tn.x * inv, tn.y * inv);
    __half2 h23 = __floats2half2_rn(tn.z * inv, tn.w * inv);
    uint2 u;
    u.x = *(unsigned int*)&h01;
    u.y = *(unsigned int*)&h23;
    ((uint2*)(Hdst + row * HALF))[lane16] = u;
}

// m = 1: fp32 gather of x; T1 = s - x; acc init; T1 mirror scaled from max|x|
__global__ void __launch_bounds__(256) cheb_first_h(const float* __restrict__ x, int hoff, int h) {
    int gw = (blockIdx.x * blockDim.x + threadIdx.x) >> 5;
    if (gw >= NWARPS) return;
    int lane = threadIdx.x & 31;
    int row = 2 * gw + (lane >> 4);
    int lane16 = lane & 15;
    float4 s = spmm_half(x, hoff, g_rowptr[row], g_rowptr[row + 1], lane16);
    size_t off = (size_t)row * HID + hoff;
    float4 xr = __ldg((const float4*)(x + off) + lane16);
    float w0 = g_w[0], w1 = g_w[1], al = g_w[16];
    float ca = w0 - w1 - al, cb = w1 + 0.5f * al;
    float4 t1, a;
    t1.x = s.x - xr.x; t1.y = s.y - xr.y; t1.z = s.z - xr.z; t1.w = s.w - xr.w;
    a.x = fmaf(ca, xr.x, cb * s.x); a.y = fmaf(ca, xr.y, cb * s.y);
    a.z = fmaf(ca, xr.z, cb * s.z); a.w = fmaf(ca, xr.w, cb * s.w);
    ((float4*)(g_B0 + off))[lane16] = t1;
    stcs4((float4*)(g_acc + off) + lane16, a);
    tn_max_update(t1, &g_maxbits[h][1]);
    unsigned int eS = (g_maxx >> 23) + 8u;
    mirror_write(g_Ha, row, lane16, t1, eS);
    if (threadIdx.x == 0 && blockIdx.x == 0) g_sexp[h][1] = eS;
}

// Step m >= 2: fp16 gather of T_{m-1} mirror; fp32 recurrence; mirror T_m.
// MODE 0: plain; MODE 1: tri-acc; MODE 2: last (writes out, no mirror/max)
template<int MODE, bool MIRROR>
__global__ void __launch_bounds__(256) cheb_step_t(const float* __restrict__ Tcur,
                                                   const float* Tprev, float* Tnew,
                                                   float* __restrict__ out,
                                                   const __half* __restrict__ Hsrc,
                                                   __half* Hdst,
                                                   int hoff, int m, int h) {
    int gw = (blockIdx.x * blockDim.x + threadIdx.x) >> 5;
    if (gw >= NWARPS) return;
    int lane = threadIdx.x & 31;
    int row = 2 * gw + (lane >> 4);
    int lane16 = lane & 15;
    float4 s = spmm_half_f16(Hsrc, g_rowptr[row], g_rowptr[row + 1], lane16);
    float scale = __uint_as_float(g_sexp[h][m - 1] << 23);   // 2^(eS-127)
    s.x *= scale; s.y *= scale; s.z *= scale; s.w *= scale;
    size_t off = (size_t)row * HID + hoff;
    float4 tc = __ldg((const float4*)(Tcur + off) + lane16);
    float4 tp = ldcs4((const float4*)(Tprev + off) + lane16);  // dead after read
    float4 tn;
    tn.x = 2.f * s.x - 2.f * tc.x - tp.x;
    tn.y = 2.f * s.y - 2.f * tc.y - tp.y;
    tn.z = 2.f * s.z - 2.f * tc.z - tp.z;
    tn.w = 2.f * s.w - 2.f * tc.w - tp.w;
    if (MODE != 2) tn_max_update(tn, &g_maxbits[h][m]);
    if (MIRROR) {
        unsigned int eS = (g_maxbits[h][m - 1] >> 23) + 8u;
        mirror_write(Hdst, row, lane16, tn, eS);
        if (threadIdx.x == 0 && blockIdx.x == 0) g_sexp[h][m] = eS;
    }
    if (MODE == 0) {
        ((float4*)(Tnew + off))[lane16] = tn;
    } else if (MODE == 1) {
        ((float4*)(Tnew + off))[lane16] = tn;
        float wa = g_w[m - 2], wb = g_w[m - 1], wc = g_w[m];
        float4 a = ldcs4((const float4*)(g_acc + off) + lane16);
        a.x = fmaf(wa, tp.x, fmaf(wb, tc.x, fmaf(wc, tn.x, a.x)));
        a.y = fmaf(wa, tp.y, fmaf(wb, tc.y, fmaf(wc, tn.y, a.y)));
        a.z = fmaf(wa, tp.z, fmaf(wb, tc.z, fmaf(wc, tn.z, a.z)));
        a.w = fmaf(wa, tp.w, fmaf(wb, tc.w, fmaf(wc, tn.w, a.w)));
        stcs4((float4*)(g_acc + off) + lane16, a);
    } else {
        float wb = g_w[m - 1], wc = g_w[m];
        float4 a = ldcs4((const float4*)(g_acc + off) + lane16);
        float4 o;
        o.x = -fmaf(wb, tc.x, fmaf(wc, tn.x, a.x));
        o.y = -fmaf(wb, tc.y, fmaf(wc, tn.y, a.y));
        o.z = -fmaf(wb, tc.z, fmaf(wc, tn.z, a.z));
        o.w = -fmaf(wb, tc.w, fmaf(wc, tn.w, a.w));
        stcs4((float4*)(out + off) + lane16, o);
    }
}

// ---------------- host ----------------
extern "C" void kernel_launch(void* const* d_in, const int* in_sizes, int n_in,
                              void* d_out, int out_size) {
    const float* x      = (const float*)d_in[0];
    const float* vals   = (const float*)d_in[1];
    const float* logits = (const float*)d_in[2];
    const float* alpha  = (const float*)d_in[3];
    const void*  erow   = d_in[4];
    const void*  ecol   = d_in[5];
    float* out = (float*)d_out;
    (void)in_sizes; (void)n_in; (void)out_size;

    void *cntp, *b0p, *b1p, *hap, *hbp;
    cudaGetSymbolAddress(&cntp, g_cnt);
    cudaGetSymbolAddress(&b0p, g_B0);
    cudaGetSymbolAddress(&b1p, g_B1);
    cudaGetSymbolAddress(&hap, g_Ha);
    cudaGetSymbolAddress(&hbp, g_Hb);

    cudaMemsetAsync(cntp, 0, NROWS * sizeof(int), 0);
    detect_k<<<1, 32>>>((const unsigned int*)erow);
    maxx_k<<<592, 256>>>((const float4*)x);
    hist_k<<<(NNZV + 255) / 256, 256>>>(erow);
    int nb = (NROWS + 1023) / 1024;
    scan_local_k<<<nb, 256>>>();
    scan_bsum_k<<<1, 256>>>(nb, logits, alpha);
    scan_add_k<<<(NROWS + 255) / 256, 256>>>();
    scatter_k<<<(NNZV + 255) / 256, 256>>>(erow, ecol, vals);

    int grid = (NWARPS * 32 + 255) / 256;   // 12500 blocks

    for (int h = 0; h < 2; ++h) {
        int hoff = h * HALF;
        cheb_first_h<<<grid, 256>>>(x, hoff, h);
        const float* Tprev = x;
        float* Tcur = (float*)b0p;
        float* Bother = (float*)b1p;
        const __half* Hsrc = (const __half*)hap;
        __half* Hdst = (__half*)hbp;
        for (int m = 2; m <= 15; ++m) {
            float* Tnew = (m == 2) ? Bother : (float*)Tprev;  // overwrite T_{m-2} (row-local safe)
            if (m == 15)
                cheb_step_t<2, false><<<grid, 256>>>(Tcur, Tprev, Tnew, out, Hsrc, Hdst, hoff, m, h);
            else if (m == 4 || m == 7 || m == 10 || m == 13)
                cheb_step_t<1, true><<<grid, 256>>>(Tcur, Tprev, Tnew, out, Hsrc, Hdst, hoff, m, h);
            else
                cheb_step_t<0, true><<<grid, 256>>>(Tcur, Tprev, Tnew, out, Hsrc, Hdst, hoff, m, h);
            Tprev = Tcur;
            Tcur = Tnew;
            const __half* t = Hsrc; Hsrc = Hdst; Hdst = (__half*)t;
        }
    }
}

// round 11
// speedup vs baseline: 2.5439x; 2.5439x over previous
#include <cuda_runtime.h>
#include <cuda_fp16.h>

#define NROWS 200000
#define NNZV  3200000
#define HID   128
#define HALF  64
#define NWARPS (NROWS / 2)   // two rows per warp

// ---------------- static device scratch (no runtime allocation) ----------------
__device__ int   g_cnt[NROWS];
__device__ int   g_rowptr[NROWS + 1];
__device__ int   g_cursor[NROWS];
__device__ int2  g_edge[NNZV];          // packed {col, val_bits}
__device__ float g_B0[NROWS * HID];
__device__ float g_B1[NROWS * HID];
__device__ float g_acc[NROWS * HID];
__device__ __half g_Ha[NROWS * HALF];   // fp16 mirror ping
__device__ __half g_Hb[NROWS * HALF];   // fp16 mirror pong
__device__ unsigned int g_maxbits2[2][32];  // atomic targets (own line per half)
__device__ unsigned int g_sexpA[2][32];     // finalized scale exponent fields (separate line)
__device__ unsigned int g_maxx;             // max|x| bits
__device__ float g_w[20];
__device__ int   g_bsum[256];
__device__ int   g_is64;

// ---------------- cache-hint load/store helpers ----------------
__device__ __forceinline__ float4 ldcs4(const float4* p) {
    float4 r;
    asm volatile("ld.global.cs.v4.f32 {%0,%1,%2,%3}, [%4];"
                 : "=f"(r.x), "=f"(r.y), "=f"(r.z), "=f"(r.w) : "l"(p));
    return r;
}
__device__ __forceinline__ void stcs4(float4* p, float4 v) {
    asm volatile("st.global.cs.v4.f32 [%0], {%1,%2,%3,%4};"
                 :: "l"(p), "f"(v.x), "f"(v.y), "f"(v.z), "f"(v.w));
}

// ---------------- index dtype detection (int32 vs int64 edges) ----------------
__device__ __forceinline__ int edge_at(const void* p, int i) {
    return g_is64 ? (int)((const long long*)p)[i] : ((const int*)p)[i];
}

__global__ void detect_k(const unsigned int* p) {
    int t = threadIdx.x;
    if (t == 0) {
        int nz = 0;
        for (int i = 1; i < 128; i += 2) nz |= (p[i] != 0u);
        g_is64 = nz ? 0 : 1;
        g_maxx = 0u;
    }
    if (t < 32) {
        g_maxbits2[0][t] = 0u; g_maxbits2[1][t] = 0u;
        g_sexpA[0][t] = 0u;    g_sexpA[1][t] = 0u;
    }
}

// ---------------- max|x| over the whole feature matrix ----------------
__global__ void maxx_k(const float4* __restrict__ x) {
    int i = blockIdx.x * blockDim.x + threadIdx.x;
    float m = 0.f;
    int n4 = NROWS * HID / 4;
    for (; i < n4; i += gridDim.x * blockDim.x) {
        float4 a = __ldg(x + i);
        m = fmaxf(m, fmaxf(fmaxf(fabsf(a.x), fabsf(a.y)), fmaxf(fabsf(a.z), fabsf(a.w))));
    }
    #pragma unroll
    for (int d = 16; d > 0; d >>= 1)
        m = fmaxf(m, __shfl_xor_sync(0xffffffffu, m, d));
    if ((threadIdx.x & 31) == 0) atomicMax(&g_maxx, __float_as_uint(m));
}

// finalize scale exponent for slot: sexpA[h][slot] = exp(maxbits2[h][slot]) + 8
// slot 0 comes from g_maxx (both halves).
__global__ void finalize_k(int h, int slot) {
    if (threadIdx.x == 0) {
        unsigned int b = (slot == 0) ? g_maxx : g_maxbits2[h][slot];
        g_sexpA[h][slot] = (b >> 23) + 8u;
    }
}

// ---------------- CSR build: histogram -> scan -> scatter ----------------
__global__ void hist_k(const void* rowp) {
    int i = blockIdx.x * blockDim.x + threadIdx.x;
    if (i < NNZV) atomicAdd(&g_cnt[edge_at(rowp, i)], 1);
}

__global__ void scan_local_k() {
    int t = threadIdx.x;
    int base = blockIdx.x * 1024 + t * 4;
    int v0 = (base + 0 < NROWS) ? g_cnt[base + 0] : 0;
    int v1 = (base + 1 < NROWS) ? g_cnt[base + 1] : 0;
    int v2 = (base + 2 < NROWS) ? g_cnt[base + 2] : 0;
    int v3 = (base + 3 < NROWS) ? g_cnt[base + 3] : 0;
    int tsum = v0 + v1 + v2 + v3;
    int inc = tsum;
    #pragma unroll
    for (int d = 1; d < 32; d <<= 1) {
        int u = __shfl_up_sync(0xffffffffu, inc, d);
        if ((t & 31) >= d) inc += u;
    }
    __shared__ int wsum[8], woff[8];
    if ((t & 31) == 31) wsum[t >> 5] = inc;
    __syncthreads();
    if (t == 0) {
        int s = 0;
        for (int i = 0; i < 8; i++) { woff[i] = s; s += wsum[i]; }
        g_bsum[blockIdx.x] = s;
    }
    __syncthreads();
    int ex = inc - tsum + woff[t >> 5];
    if (base + 0 < NROWS) g_rowptr[base + 0] = ex;
    if (base + 1 < NROWS) g_rowptr[base + 1] = ex + v0;
    if (base + 2 < NROWS) g_rowptr[base + 2] = ex + v0 + v1;
    if (base + 3 < NROWS) g_rowptr[base + 3] = ex + v0 + v1 + v2;
}

__global__ void scan_bsum_k(int nb, const float* __restrict__ logits,
                            const float* __restrict__ alpha) {
    int t = threadIdx.x;
    int v = (t < nb) ? g_bsum[t] : 0;
    int inc = v;
    #pragma unroll
    for (int d = 1; d < 32; d <<= 1) {
        int u = __shfl_up_sync(0xffffffffu, inc, d);
        if ((t & 31) >= d) inc += u;
    }
    __shared__ int ws[8], wo[8];
    if ((t & 31) == 31) ws[t >> 5] = inc;
    __syncthreads();
    if (t == 0) {
        int s = 0;
        for (int i = 0; i < 8; i++) { wo[i] = s; s += ws[i]; }
    }
    __syncthreads();
    if (t < nb) g_bsum[t] = inc - v + wo[t >> 5];
    if (t == 224) {
        float m = logits[0];
        for (int i = 1; i < 16; i++) m = fmaxf(m, logits[i]);
        float e[16], s = 0.f;
        for (int i = 0; i < 16; i++) { e[i] = __expf(logits[i] - m); s += e[i]; }
        float inv = 1.f / s;
        for (int i = 0; i < 16; i++) g_w[i] = e[i] * inv;
        g_w[16] = *alpha;
    }
}

__global__ void scan_add_k() {
    int i = blockIdx.x * blockDim.x + threadIdx.x;
    if (i < NROWS) {
        int v = g_rowptr[i] + g_bsum[i >> 10];
        g_rowptr[i] = v;
        g_cursor[i] = v;
        if (i == 0) g_rowptr[NROWS] = NNZV;
    }
}

__global__ void scatter_k(const void* rowp, const void* colp, const float* __restrict__ v) {
    int i = blockIdx.x * blockDim.x + threadIdx.x;
    if (i < NNZV) {
        int r = edge_at(rowp, i);
        int p = atomicAdd(&g_cursor[r], 1);
        g_edge[p] = make_int2(edge_at(colp, i), __float_as_int(v[i]));
    }
}

// ---------------- gathers ----------------
__device__ __forceinline__ float4 spmm_half(const float* __restrict__ srcf, int hoff,
                                            int beg, int end, int lane16) {
    float4 s = make_float4(0.f, 0.f, 0.f, 0.f);
    #pragma unroll 4
    for (int j = beg; j < end; ++j) {
        int2 e = __ldg(g_edge + j);
        float v = __int_as_float(e.y);
        const float4* p = (const float4*)(srcf + e.x * HID + hoff) + lane16;
        float4 a = __ldg(p);
        s.x = fmaf(v, a.x, s.x); s.y = fmaf(v, a.y, s.y);
        s.z = fmaf(v, a.z, s.z); s.w = fmaf(v, a.w, s.w);
    }
    return s;
}

__device__ __forceinline__ float4 spmm_half_f16(const __half* __restrict__ H,
                                                int beg, int end, int lane16) {
    float4 s = make_float4(0.f, 0.f, 0.f, 0.f);
    #pragma unroll 4
    for (int j = beg; j < end; ++j) {
        int2 e = __ldg(g_edge + j);
        float v = __int_as_float(e.y);
        const uint2* p = (const uint2*)(H + (size_t)e.x * HALF) + lane16;
        uint2 u = __ldg(p);
        __half2 h01 = *(__half2*)&u.x;
        __half2 h23 = *(__half2*)&u.y;
        float2 f01 = __half22float2(h01);
        float2 f23 = __half22float2(h23);
        s.x = fmaf(v, f01.x, s.x); s.y = fmaf(v, f01.y, s.y);
        s.z = fmaf(v, f23.x, s.z); s.w = fmaf(v, f23.y, s.w);
    }
    return s;
}

// block-level max -> ONE atomic per block
__device__ __forceinline__ void block_max(float4 tn, unsigned int* slot) {
    float m = fmaxf(fmaxf(fabsf(tn.x), fabsf(tn.y)), fmaxf(fabsf(tn.z), fabsf(tn.w)));
    #pragma unroll
    for (int d = 16; d > 0; d >>= 1)
        m = fmaxf(m, __shfl_xor_sync(0xffffffffu, m, d));
    __shared__ float wmax[8];
    int wid = threadIdx.x >> 5;
    if ((threadIdx.x & 31) == 0) wmax[wid] = m;
    __syncthreads();
    if (wid == 0) {
        float v = ((threadIdx.x & 31) < 8) ? wmax[threadIdx.x & 31] : 0.f;
        #pragma unroll
        for (int d = 4; d > 0; d >>= 1)
            v = fmaxf(v, __shfl_xor_sync(0xffffffffu, v, d));
        if (threadIdx.x == 0) atomicMax(slot, __float_as_uint(v));
    }
}

__device__ __forceinline__ void mirror_write(__half* Hdst, size_t row, int lane16,
                                             float4 tn, unsigned int eS) {
    float inv = __uint_as_float((254u - eS) << 23);   // 2^(127-eS)
    __half2 h01 = __floats2half2_rn(tn.x * inv, tn.y * inv);
    __half2 h23 = __floats2half2_rn(tn.z * inv, tn.w * inv);
    uint2 u;
    u.x = *(unsigned int*)&h01;
    u.y = *(unsigned int*)&h23;
    ((uint2*)(Hdst + row * HALF))[lane16] = u;
}

// m = 1: fp32 gather of x; T1 = s - x; acc init; mirror T1 (scale slot 0 = max|x|); block-max T1 -> slot 1
__global__ void __launch_bounds__(256) cheb_first_h(const float* __restrict__ x, int hoff, int h) {
    int gw = (blockIdx.x * blockDim.x + threadIdx.x) >> 5;
    int lane = threadIdx.x & 31;
    int row = 2 * gw + (lane >> 4);
    int lane16 = lane & 15;
    float4 s = spmm_half(x, hoff, g_rowptr[row], g_rowptr[row + 1], lane16);
    size_t off = (size_t)row * HID + hoff;
    float4 xr = __ldg((const float4*)(x + off) + lane16);
    float w0 = g_w[0], w1 = g_w[1], al = g_w[16];
    float ca = w0 - w1 - al, cb = w1 + 0.5f * al;
    float4 t1, a;
    t1.x = s.x - xr.x; t1.y = s.y - xr.y; t1.z = s.z - xr.z; t1.w = s.w - xr.w;
    a.x = fmaf(ca, xr.x, cb * s.x); a.y = fmaf(ca, xr.y, cb * s.y);
    a.z = fmaf(ca, xr.z, cb * s.z); a.w = fmaf(ca, xr.w, cb * s.w);
    ((float4*)(g_B0 + off))[lane16] = t1;
    stcs4((float4*)(g_acc + off) + lane16, a);
    mirror_write(g_Ha, row, lane16, t1, g_sexpA[h][0]);
    block_max(t1, &g_maxbits2[h][1]);
}

// Step m >= 2: fp16 gather; fp32 recurrence; mirror T_m with finalized slot_w.
// MODE 0: plain; MODE 1: tri-acc; MODE 2: last. DOMAX: block-max into maxbits2[h][m].
template<int MODE, bool MIRROR, bool DOMAX>
__global__ void __launch_bounds__(256) cheb_step_t(const float* __restrict__ Tcur,
                                                   const float* Tprev, float* Tnew,
                                                   float* __restrict__ out,
                                                   const __half* __restrict__ Hsrc,
                                                   __half* Hdst,
                                                   int hoff, int m, int h,
                                                   int slot_r, int slot_w) {
    int gw = (blockIdx.x * blockDim.x + threadIdx.x) >> 5;
    int lane = threadIdx.x & 31;
    int row = 2 * gw + (lane >> 4);
    int lane16 = lane & 15;
    float4 s = spmm_half_f16(Hsrc, g_rowptr[row], g_rowptr[row + 1], lane16);
    float scale = __uint_as_float(g_sexpA[h][slot_r] << 23);   // 2^(eS-127)
    s.x *= scale; s.y *= scale; s.z *= scale; s.w *= scale;
    size_t off = (size_t)row * HID + hoff;
    float4 tc = __ldg((const float4*)(Tcur + off) + lane16);
    float4 tp = ldcs4((const float4*)(Tprev + off) + lane16);  // dead after read
    float4 tn;
    tn.x = 2.f * s.x - 2.f * tc.x - tp.x;
    tn.y = 2.f * s.y - 2.f * tc.y - tp.y;
    tn.z = 2.f * s.z - 2.f * tc.z - tp.z;
    tn.w = 2.f * s.w - 2.f * tc.w - tp.w;
    if (MIRROR) mirror_write(Hdst, row, lane16, tn, g_sexpA[h][slot_w]);
    if (MODE == 0) {
        ((float4*)(Tnew + off))[lane16] = tn;
    } else if (MODE == 1) {
        ((float4*)(Tnew + off))[lane16] = tn;
        float wa = g_w[m - 2], wb = g_w[m - 1], wc = g_w[m];
        float4 a = ldcs4((const float4*)(g_acc + off) + lane16);
        a.x = fmaf(wa, tp.x, fmaf(wb, tc.x, fmaf(wc, tn.x, a.x)));
        a.y = fmaf(wa, tp.y, fmaf(wb, tc.y, fmaf(wc, tn.y, a.y)));
        a.z = fmaf(wa, tp.z, fmaf(wb, tc.z, fmaf(wc, tn.z, a.z)));
        a.w = fmaf(wa, tp.w, fmaf(wb, tc.w, fmaf(wc, tn.w, a.w)));
        stcs4((float4*)(g_acc + off) + lane16, a);
    } else {
        float wb = g_w[m - 1], wc = g_w[m];
        float4 a = ldcs4((const float4*)(g_acc + off) + lane16);
        float4 o;
        o.x = -fmaf(wb, tc.x, fmaf(wc, tn.x, a.x));
        o.y = -fmaf(wb, tc.y, fmaf(wc, tn.y, a.y));
        o.z = -fmaf(wb, tc.z, fmaf(wc, tn.z, a.z));
        o.w = -fmaf(wb, tc.w, fmaf(wc, tn.w, a.w));
        stcs4((float4*)(out + off) + lane16, o);
    }
    if (DOMAX) block_max(tn, &g_maxbits2[h][m]);
}

// ---------------- host ----------------
extern "C" void kernel_launch(void* const* d_in, const int* in_sizes, int n_in,
                              void* d_out, int out_size) {
    const float* x      = (const float*)d_in[0];
    const float* vals   = (const float*)d_in[1];
    const float* logits = (const float*)d_in[2];
    const float* alpha  = (const float*)d_in[3];
    const void*  erow   = d_in[4];
    const void*  ecol   = d_in[5];
    float* out = (float*)d_out;
    (void)in_sizes; (void)n_in; (void)out_size;

    void *cntp, *b0p, *b1p, *hap, *hbp;
    cudaGetSymbolAddress(&cntp, g_cnt);
    cudaGetSymbolAddress(&b0p, g_B0);
    cudaGetSymbolAddress(&b1p, g_B1);
    cudaGetSymbolAddress(&hap, g_Ha);
    cudaGetSymbolAddress(&hbp, g_Hb);

    cudaMemsetAsync(cntp, 0, NROWS * sizeof(int), 0);
    detect_k<<<1, 32>>>((const unsigned int*)erow);
    maxx_k<<<592, 256>>>((const float4*)x);
    hist_k<<<(NNZV + 255) / 256, 256>>>(erow);
    int nb = (NROWS + 1023) / 1024;
    scan_local_k<<<nb, 256>>>();
    scan_bsum_k<<<1, 256>>>(nb, logits, alpha);
    scan_add_k<<<(NROWS + 255) / 256, 256>>>();
    scatter_k<<<(NNZV + 255) / 256, 256>>>(erow, ecol, vals);

    int grid = (NWARPS * 32 + 255) / 256;   // 12500 blocks, exact coverage

    // slot_w[m]: latest finalized max slot before kernel m (0 = max|x|)
    auto slotw = [](int m) { return m <= 1 ? 0 : (m <= 4 ? 1 : (m <= 7 ? 4 : (m <= 10 ? 7 : (m <= 13 ? 10 : 13)))); };

    for (int h = 0; h < 2; ++h) {
        int hoff = h * HALF;
        finalize_k<<<1, 32>>>(h, 0);                 // slot 0 from max|x|
        cheb_first_h<<<grid, 256>>>(x, hoff, h);     // mirrors T1 (slot 0), block-max -> slot 1
        finalize_k<<<1, 32>>>(h, 1);
        const float* Tprev = x;
        float* Tcur = (float*)b0p;
        float* Bother = (float*)b1p;
        const __half* Hsrc = (const __half*)hap;
        __half* Hdst = (__half*)hbp;
        for (int m = 2; m <= 15; ++m) {
            float* Tnew = (m == 2) ? Bother : (float*)Tprev;  // overwrite T_{m-2} (row-local safe)
            int sr = slotw(m - 1), sw = slotw(m);
            if (m == 15)
                cheb_step_t<2, false, false><<<grid, 256>>>(Tcur, Tprev, Tnew, out, Hsrc, Hdst, hoff, m, h, sr, sw);
            else if (m == 4 || m == 7 || m == 10 || m == 13) {
                cheb_step_t<1, true, true><<<grid, 256>>>(Tcur, Tprev, Tnew, out, Hsrc, Hdst, hoff, m, h, sr, sw);
                finalize_k<<<1, 32>>>(h, m);         // finalize slot m for steps m+1..m+3
            } else
                cheb_step_t<0, true, false><<<grid, 256>>>(Tcur, Tprev, Tnew, out, Hsrc, Hdst, hoff, m, h, sr, sw);
            Tprev = Tcur;
            Tcur = Tnew;
            const __half* t = Hsrc; Hsrc = Hdst; Hdst = (__half*)t;
        }
    }
}

// round 12
// speedup vs baseline: 2.7503x; 1.0811x over previous
#include <cuda_runtime.h>
#include <cuda_fp16.h>

#define NROWS 200000
#define NNZV  3200000
#define HID   128

// ---------------- static device scratch (no runtime allocation) ----------------
__device__ int   g_cnt[NROWS];
__device__ int   g_rowptr[NROWS + 1];
__device__ int   g_cursor[NROWS];
__device__ int2  g_edge[NNZV];          // packed {col, val_bits}
__device__ float g_B0[NROWS * HID];
__device__ float g_B1[NROWS * HID];
__device__ float g_acc[NROWS * HID];
__device__ __half g_Hx[NROWS * HID];    // fp16 mirror of x
__device__ __half g_Ha[NROWS * HID];    // fp16 mirror ping
__device__ __half g_Hb[NROWS * HID];    // fp16 mirror pong
__device__ unsigned int g_maxbits2[32]; // atomic max targets
__device__ unsigned int g_sexpA[32];    // finalized scale exponent fields (separate line)
__device__ unsigned int g_maxx;         // max|x| bits
__device__ float g_w[20];
__device__ int   g_bsum[256];
__device__ int   g_is64;

// ---------------- cache-hint load/store helpers ----------------
__device__ __forceinline__ float4 ldcs4(const float4* p) {
    float4 r;
    asm volatile("ld.global.cs.v4.f32 {%0,%1,%2,%3}, [%4];"
                 : "=f"(r.x), "=f"(r.y), "=f"(r.z), "=f"(r.w) : "l"(p));
    return r;
}
__device__ __forceinline__ void stcs4(float4* p, float4 v) {
    asm volatile("st.global.cs.v4.f32 [%0], {%1,%2,%3,%4};"
                 :: "l"(p), "f"(v.x), "f"(v.y), "f"(v.z), "f"(v.w));
}

// ---------------- index dtype detection (int32 vs int64 edges) ----------------
__device__ __forceinline__ int edge_at(const void* p, int i) {
    return g_is64 ? (int)((const long long*)p)[i] : ((const int*)p)[i];
}

__global__ void detect_k(const unsigned int* p) {
    int t = threadIdx.x;
    if (t == 0) {
        int nz = 0;
        for (int i = 1; i < 128; i += 2) nz |= (p[i] != 0u);
        g_is64 = nz ? 0 : 1;
        g_maxx = 0u;
    }
    if (t < 32) { g_maxbits2[t] = 0u; g_sexpA[t] = 0u; }
}

// ---------------- max|x| ----------------
__global__ void maxx_k(const float4* __restrict__ x) {
    int i = blockIdx.x * blockDim.x + threadIdx.x;
    float m = 0.f;
    int n4 = NROWS * HID / 4;
    for (; i < n4; i += gridDim.x * blockDim.x) {
        float4 a = __ldg(x + i);
        m = fmaxf(m, fmaxf(fmaxf(fabsf(a.x), fabsf(a.y)), fmaxf(fabsf(a.z), fabsf(a.w))));
    }
    #pragma unroll
    for (int d = 16; d > 0; d >>= 1)
        m = fmaxf(m, __shfl_xor_sync(0xffffffffu, m, d));
    if ((threadIdx.x & 31) == 0) atomicMax(&g_maxx, __float_as_uint(m));
}

// finalize scale exponent: sexpA[slot] = exp(src) + 8 (slot 0 from g_maxx)
__global__ void finalize_k(int slot) {
    if (threadIdx.x == 0) {
        unsigned int b = (slot == 0) ? g_maxx : g_maxbits2[slot];
        g_sexpA[slot] = (b >> 23) + 8u;
    }
}

// x -> fp16 mirror (scale slot 0)
__global__ void xmirror_k(const float4* __restrict__ x) {
    int i = blockIdx.x * blockDim.x + threadIdx.x;
    int n4 = NROWS * HID / 4;
    unsigned int eS = g_sexpA[0];
    float inv = __uint_as_float((254u - eS) << 23);
    for (; i < n4; i += gridDim.x * blockDim.x) {
        float4 a = __ldg(x + i);
        __half2 h01 = __floats2half2_rn(a.x * inv, a.y * inv);
        __half2 h23 = __floats2half2_rn(a.z * inv, a.w * inv);
        uint2 u;
        u.x = *(unsigned int*)&h01;
        u.y = *(unsigned int*)&h23;
        ((uint2*)g_Hx)[i] = u;
    }
}

// ---------------- CSR build ----------------
__global__ void hist_k(const void* rowp) {
    int i = blockIdx.x * blockDim.x + threadIdx.x;
    if (i < NNZV) atomicAdd(&g_cnt[edge_at(rowp, i)], 1);
}

__global__ void scan_local_k() {
    int t = threadIdx.x;
    int base = blockIdx.x * 1024 + t * 4;
    int v0 = (base + 0 < NROWS) ? g_cnt[base + 0] : 0;
    int v1 = (base + 1 < NROWS) ? g_cnt[base + 1] : 0;
    int v2 = (base + 2 < NROWS) ? g_cnt[base + 2] : 0;
    int v3 = (base + 3 < NROWS) ? g_cnt[base + 3] : 0;
    int tsum = v0 + v1 + v2 + v3;
    int inc = tsum;
    #pragma unroll
    for (int d = 1; d < 32; d <<= 1) {
        int u = __shfl_up_sync(0xffffffffu, inc, d);
        if ((t & 31) >= d) inc += u;
    }
    __shared__ int wsum[8], woff[8];
    if ((t & 31) == 31) wsum[t >> 5] = inc;
    __syncthreads();
    if (t == 0) {
        int s = 0;
        for (int i = 0; i < 8; i++) { woff[i] = s; s += wsum[i]; }
        g_bsum[blockIdx.x] = s;
    }
    __syncthreads();
    int ex = inc - tsum + woff[t >> 5];
    if (base + 0 < NROWS) g_rowptr[base + 0] = ex;
    if (base + 1 < NROWS) g_rowptr[base + 1] = ex + v0;
    if (base + 2 < NROWS) g_rowptr[base + 2] = ex + v0 + v1;
    if (base + 3 < NROWS) g_rowptr[base + 3] = ex + v0 + v1 + v2;
}

__global__ void scan_bsum_k(int nb, const float* __restrict__ logits,
                            const float* __restrict__ alpha) {
    int t = threadIdx.x;
    int v = (t < nb) ? g_bsum[t] : 0;
    int inc = v;
    #pragma unroll
    for (int d = 1; d < 32; d <<= 1) {
        int u = __shfl_up_sync(0xffffffffu, inc, d);
        if ((t & 31) >= d) inc += u;
    }
    __shared__ int ws[8], wo[8];
    if ((t & 31) == 31) ws[t >> 5] = inc;
    __syncthreads();
    if (t == 0) {
        int s = 0;
        for (int i = 0; i < 8; i++) { wo[i] = s; s += ws[i]; }
    }
    __syncthreads();
    if (t < nb) g_bsum[t] = inc - v + wo[t >> 5];
    if (t == 224) {
        float m = logits[0];
        for (int i = 1; i < 16; i++) m = fmaxf(m, logits[i]);
        float e[16], s = 0.f;
        for (int i = 0; i < 16; i++) { e[i] = __expf(logits[i] - m); s += e[i]; }
        float inv = 1.f / s;
        for (int i = 0; i < 16; i++) g_w[i] = e[i] * inv;
        g_w[16] = *alpha;
    }
}

__global__ void scan_add_k() {
    int i = blockIdx.x * blockDim.x + threadIdx.x;
    if (i < NROWS) {
        int v = g_rowptr[i] + g_bsum[i >> 10];
        g_rowptr[i] = v;
        g_cursor[i] = v;
        if (i == 0) g_rowptr[NROWS] = NNZV;
    }
}

__global__ void scatter_k(const void* rowp, const void* colp, const float* __restrict__ v) {
    int i = blockIdx.x * blockDim.x + threadIdx.x;
    if (i < NNZV) {
        int r = edge_at(rowp, i);
        int p = atomicAdd(&g_cursor[r], 1);
        g_edge[p] = make_int2(edge_at(colp, i), __float_as_int(v[i]));
    }
}

// ---------------- full-width fp16 gather: warp-per-row, lane owns 4 channels ----------------
__device__ __forceinline__ float4 spmm_f16(const __half* __restrict__ H,
                                           int beg, int end, int lane) {
    float4 s = make_float4(0.f, 0.f, 0.f, 0.f);
    #pragma unroll 4
    for (int j = beg; j < end; ++j) {
        int2 e = __ldg(g_edge + j);
        float v = __int_as_float(e.y);
        const uint2* p = (const uint2*)(H + (size_t)e.x * HID) + lane;
        uint2 u = __ldg(p);
        __half2 h01 = *(__half2*)&u.x;
        __half2 h23 = *(__half2*)&u.y;
        float2 f01 = __half22float2(h01);
        float2 f23 = __half22float2(h23);
        s.x = fmaf(v, f01.x, s.x); s.y = fmaf(v, f01.y, s.y);
        s.z = fmaf(v, f23.x, s.z); s.w = fmaf(v, f23.y, s.w);
    }
    return s;
}

// block-level max -> ONE atomic per block
__device__ __forceinline__ void block_max(float4 tn, unsigned int* slot) {
    float m = fmaxf(fmaxf(fabsf(tn.x), fabsf(tn.y)), fmaxf(fabsf(tn.z), fabsf(tn.w)));
    #pragma unroll
    for (int d = 16; d > 0; d >>= 1)
        m = fmaxf(m, __shfl_xor_sync(0xffffffffu, m, d));
    __shared__ float wmax[8];
    int wid = threadIdx.x >> 5;
    if ((threadIdx.x & 31) == 0) wmax[wid] = m;
    __syncthreads();
    if (wid == 0) {
        float v = ((threadIdx.x & 31) < 8) ? wmax[threadIdx.x & 31] : 0.f;
        #pragma unroll
        for (int d = 4; d > 0; d >>= 1)
            v = fmaxf(v, __shfl_xor_sync(0xffffffffu, v, d));
        if (threadIdx.x == 0) atomicMax(slot, __float_as_uint(v));
    }
}

__device__ __forceinline__ void mirror_write(__half* Hdst, size_t row, int lane,
                                             float4 tn, unsigned int eS) {
    float inv = __uint_as_float((254u - eS) << 23);   // 2^(127-eS)
    __half2 h01 = __floats2half2_rn(tn.x * inv, tn.y * inv);
    __half2 h23 = __floats2half2_rn(tn.z * inv, tn.w * inv);
    uint2 u;
    u.x = *(unsigned int*)&h01;
    u.y = *(unsigned int*)&h23;
    ((uint2*)(Hdst + row * HID))[lane] = u;
}

// m = 1: fp16 gather of x-mirror; T1 = s - x; acc init; mirror T1 (slot 0); block-max -> slot 1
__global__ void __launch_bounds__(256) cheb_first_k(const float* __restrict__ x) {
    int row = (blockIdx.x * blockDim.x + threadIdx.x) >> 5;
    int lane = threadIdx.x & 31;
    float4 s = spmm_f16(g_Hx, g_rowptr[row], g_rowptr[row + 1], lane);
    float scale = __uint_as_float(g_sexpA[0] << 23);
    s.x *= scale; s.y *= scale; s.z *= scale; s.w *= scale;
    size_t off = (size_t)row * HID;
    float4 xr = __ldg((const float4*)(x + off) + lane);
    float w0 = g_w[0], w1 = g_w[1], al = g_w[16];
    float ca = w0 - w1 - al, cb = w1 + 0.5f * al;
    float4 t1, a;
    t1.x = s.x - xr.x; t1.y = s.y - xr.y; t1.z = s.z - xr.z; t1.w = s.w - xr.w;
    a.x = fmaf(ca, xr.x, cb * s.x); a.y = fmaf(ca, xr.y, cb * s.y);
    a.z = fmaf(ca, xr.z, cb * s.z); a.w = fmaf(ca, xr.w, cb * s.w);
    ((float4*)(g_B0 + off))[lane] = t1;
    stcs4((float4*)(g_acc + off) + lane, a);
    mirror_write(g_Ha, row, lane, t1, g_sexpA[0]);
    block_max(t1, &g_maxbits2[1]);
}

// Step m >= 2: fp16 gather; fp32 recurrence; mirror T_m (slot_w).
// MODE 0: plain; MODE 1: tri-acc; MODE 2: last. DOMAX: block-max into maxbits2[m].
template<int MODE, bool MIRROR, bool DOMAX>
__global__ void __launch_bounds__(256) cheb_step_t(const float* __restrict__ Tcur,
                                                   const float* Tprev, float* Tnew,
                                                   float* __restrict__ out,
                                                   const __half* __restrict__ Hsrc,
                                                   __half* Hdst,
                                                   int m, int slot_r, int slot_w) {
    int row = (blockIdx.x * blockDim.x + threadIdx.x) >> 5;
    int lane = threadIdx.x & 31;
    float4 s = spmm_f16(Hsrc, g_rowptr[row], g_rowptr[row + 1], lane);
    float scale = __uint_as_float(g_sexpA[slot_r] << 23);   // 2^(eS-127)
    s.x *= scale; s.y *= scale; s.z *= scale; s.w *= scale;
    size_t off = (size_t)row * HID;
    float4 tc = __ldg((const float4*)(Tcur + off) + lane);
    float4 tp = ldcs4((const float4*)(Tprev + off) + lane);  // dead after read
    float4 tn;
    tn.x = 2.f * s.x - 2.f * tc.x - tp.x;
    tn.y = 2.f * s.y - 2.f * tc.y - tp.y;
    tn.z = 2.f * s.z - 2.f * tc.z - tp.z;
    tn.w = 2.f * s.w - 2.f * tc.w - tp.w;
    if (MIRROR) mirror_write(Hdst, row, lane, tn, g_sexpA[slot_w]);
    if (MODE == 0) {
        ((float4*)(Tnew + off))[lane] = tn;
    } else if (MODE == 1) {
        ((float4*)(Tnew + off))[lane] = tn;
        float wa = g_w[m - 2], wb = g_w[m - 1], wc = g_w[m];
        float4 a = ldcs4((const float4*)(g_acc + off) + lane);
        a.x = fmaf(wa, tp.x, fmaf(wb, tc.x, fmaf(wc, tn.x, a.x)));
        a.y = fmaf(wa, tp.y, fmaf(wb, tc.y, fmaf(wc, tn.y, a.y)));
        a.z = fmaf(wa, tp.z, fmaf(wb, tc.z, fmaf(wc, tn.z, a.z)));
        a.w = fmaf(wa, tp.w, fmaf(wb, tc.w, fmaf(wc, tn.w, a.w)));
        stcs4((float4*)(g_acc + off) + lane, a);
    } else {
        float wb = g_w[m - 1], wc = g_w[m];
        float4 a = ldcs4((const float4*)(g_acc + off) + lane);
        float4 o;
        o.x = -fmaf(wb, tc.x, fmaf(wc, tn.x, a.x));
        o.y = -fmaf(wb, tc.y, fmaf(wc, tn.y, a.y));
        o.z = -fmaf(wb, tc.z, fmaf(wc, tn.z, a.z));
        o.w = -fmaf(wb, tc.w, fmaf(wc, tn.w, a.w));
        stcs4((float4*)(out + off) + lane, o);
    }
    if (DOMAX) block_max(tn, &g_maxbits2[m]);
}

// ---------------- host ----------------
extern "C" void kernel_launch(void* const* d_in, const int* in_sizes, int n_in,
                              void* d_out, int out_size) {
    const float* x      = (const float*)d_in[0];
    const float* vals   = (const float*)d_in[1];
    const float* logits = (const float*)d_in[2];
    const float* alpha  = (const float*)d_in[3];
    const void*  erow   = d_in[4];
    const void*  ecol   = d_in[5];
    float* out = (float*)d_out;
    (void)in_sizes; (void)n_in; (void)out_size;

    void *cntp, *b0p, *b1p, *hap, *hbp;
    cudaGetSymbolAddress(&cntp, g_cnt);
    cudaGetSymbolAddress(&b0p, g_B0);
    cudaGetSymbolAddress(&b1p, g_B1);
    cudaGetSymbolAddress(&hap, g_Ha);
    cudaGetSymbolAddress(&hbp, g_Hb);

    cudaMemsetAsync(cntp, 0, NROWS * sizeof(int), 0);
    detect_k<<<1, 32>>>((const unsigned int*)erow);
    maxx_k<<<592, 256>>>((const float4*)x);
    finalize_k<<<1, 32>>>(0);
    xmirror_k<<<592, 256>>>((const float4*)x);
    hist_k<<<(NNZV + 255) / 256, 256>>>(erow);
    int nb = (NROWS + 1023) / 1024;
    scan_local_k<<<nb, 256>>>();
    scan_bsum_k<<<1, 256>>>(nb, logits, alpha);
    scan_add_k<<<(NROWS + 255) / 256, 256>>>();
    scatter_k<<<(NNZV + 255) / 256, 256>>>(erow, ecol, vals);

    int grid = NROWS * 32 / 256;   // 25000 blocks, exact

    // slot_w[m]: latest finalized max slot before kernel m runs (0 = max|x|)
    auto slotw = [](int m) { return m <= 1 ? 0 : (m <= 4 ? 1 : (m <= 7 ? 4 : (m <= 10 ? 7 : (m <= 13 ? 10 : 13)))); };

    cheb_first_k<<<grid, 256>>>(x);
    finalize_k<<<1, 32>>>(1);

    const float* Tprev = x;
    float* Tcur = (float*)b0p;
    float* Bother = (float*)b1p;
    const __half* Hsrc = (const __half*)hap;
    __half* Hdst = (__half*)hbp;
    for (int m = 2; m <= 15; ++m) {
        float* Tnew = (m == 2) ? Bother : (float*)Tprev;  // overwrite T_{m-2} (row-local safe)
        int sr = slotw(m - 1), sw = slotw(m);
        if (m == 15)
            cheb_step_t<2, false, false><<<grid, 256>>>(Tcur, Tprev, Tnew, out, Hsrc, Hdst, m, sr, sw);
        else if (m == 4 || m == 7 || m == 10 || m == 13) {
            cheb_step_t<1, true, true><<<grid, 256>>>(Tcur, Tprev, Tnew, out, Hsrc, Hdst, m, sr, sw);
            finalize_k<<<1, 32>>>(m);                 // finalize slot m for steps m+1..m+3
        } else
            cheb_step_t<0, true, false><<<grid, 256>>>(Tcur, Tprev, Tnew, out, Hsrc, Hdst, m, sr, sw);
        Tprev = Tcur;
        Tcur = Tnew;
        const __half* t = Hsrc; Hsrc = Hdst; Hdst = (__half*)t;
    }
}

// round 13
// speedup vs baseline: 2.7924x; 1.0153x over previous
#include <cuda_runtime.h>
#include <cuda_fp16.h>

#define NROWS 200000
#define NNZV  3200000
#define HID   128

// ---------------- static device scratch (no runtime allocation) ----------------
__device__ int   g_cnt[NROWS];
__device__ int   g_rowptr[NROWS + 1];
__device__ int   g_cursor[NROWS];
__device__ int2  g_edge[NNZV];          // packed {col, val_bits}
__device__ float g_B0[NROWS * HID];
__device__ float g_B1[NROWS * HID];
__device__ float g_acc[NROWS * HID];
__device__ __half g_Ha[NROWS * HID];    // fp16 mirror ping
__device__ __half g_Hb[NROWS * HID];    // fp16 mirror pong (starts as x-mirror)
__device__ unsigned int g_maxbits2[128]; // max|T_m| slots, padded: slot i at [i*8] (32B apart)
__device__ float g_w[20];
__device__ int   g_bsum[256];
__device__ int   g_is64;

// ---------------- cache-hint load/store helpers ----------------
__device__ __forceinline__ float4 ldcs4(const float4* p) {
    float4 r;
    asm volatile("ld.global.cs.v4.f32 {%0,%1,%2,%3}, [%4];"
                 : "=f"(r.x), "=f"(r.y), "=f"(r.z), "=f"(r.w) : "l"(p));
    return r;
}
__device__ __forceinline__ void stcs4(float4* p, float4 v) {
    asm volatile("st.global.cs.v4.f32 [%0], {%1,%2,%3,%4};"
                 :: "l"(p), "f"(v.x), "f"(v.y), "f"(v.z), "f"(v.w));
}
__device__ __forceinline__ uint2 ldcs_u2(const uint2* p) {
    uint2 r;
    asm volatile("ld.global.cs.v2.u32 {%0,%1}, [%2];" : "=r"(r.x), "=r"(r.y) : "l"(p));
    return r;
}

// scale exponent field from a slot: eS = exp(maxbits) + 8
__device__ __forceinline__ unsigned int slot_sexp(int slot) {
    return (g_maxbits2[slot * 8] >> 23) + 8u;
}

// ---------------- index dtype detection (int32 vs int64 edges) ----------------
__device__ __forceinline__ int edge_at(const void* p, int i) {
    return g_is64 ? (int)((const long long*)p)[i] : ((const int*)p)[i];
}

__global__ void detect_k(const unsigned int* p) {
    int t = threadIdx.x;
    if (t == 0) {
        int nz = 0;
        for (int i = 1; i < 128; i += 2) nz |= (p[i] != 0u);
        g_is64 = nz ? 0 : 1;
    }
    if (t < 128) g_maxbits2[t] = 0u;
}

// ---------------- max|x| -> slot 0 ----------------
__global__ void maxx_k(const float4* __restrict__ x) {
    int i = blockIdx.x * blockDim.x + threadIdx.x;
    float m = 0.f;
    int n4 = NROWS * HID / 4;
    for (; i < n4; i += gridDim.x * blockDim.x) {
        float4 a = __ldg(x + i);
        m = fmaxf(m, fmaxf(fmaxf(fabsf(a.x), fabsf(a.y)), fmaxf(fabsf(a.z), fabsf(a.w))));
    }
    #pragma unroll
    for (int d = 16; d > 0; d >>= 1)
        m = fmaxf(m, __shfl_xor_sync(0xffffffffu, m, d));
    if ((threadIdx.x & 31) == 0) atomicMax(&g_maxbits2[0], __float_as_uint(m));
}

// x -> fp16 mirror in g_Hb (scale slot 0)
__global__ void xmirror_k(const float4* __restrict__ x) {
    int i = blockIdx.x * blockDim.x + threadIdx.x;
    int n4 = NROWS * HID / 4;
    unsigned int eS = slot_sexp(0);
    float inv = __uint_as_float((254u - eS) << 23);
    for (; i < n4; i += gridDim.x * blockDim.x) {
        float4 a = __ldg(x + i);
        __half2 h01 = __floats2half2_rn(a.x * inv, a.y * inv);
        __half2 h23 = __floats2half2_rn(a.z * inv, a.w * inv);
        uint2 u;
        u.x = *(unsigned int*)&h01;
        u.y = *(unsigned int*)&h23;
        ((uint2*)g_Hb)[i] = u;
    }
}

// ---------------- CSR build ----------------
__global__ void hist_k(const void* rowp) {
    int i = blockIdx.x * blockDim.x + threadIdx.x;
    if (i < NNZV) atomicAdd(&g_cnt[edge_at(rowp, i)], 1);
}

__global__ void scan_local_k() {
    int t = threadIdx.x;
    int base = blockIdx.x * 1024 + t * 4;
    int v0 = (base + 0 < NROWS) ? g_cnt[base + 0] : 0;
    int v1 = (base + 1 < NROWS) ? g_cnt[base + 1] : 0;
    int v2 = (base + 2 < NROWS) ? g_cnt[base + 2] : 0;
    int v3 = (base + 3 < NROWS) ? g_cnt[base + 3] : 0;
    int tsum = v0 + v1 + v2 + v3;
    int inc = tsum;
    #pragma unroll
    for (int d = 1; d < 32; d <<= 1) {
        int u = __shfl_up_sync(0xffffffffu, inc, d);
        if ((t & 31) >= d) inc += u;
    }
    __shared__ int wsum[8], woff[8];
    if ((t & 31) == 31) wsum[t >> 5] = inc;
    __syncthreads();
    if (t == 0) {
        int s = 0;
        for (int i = 0; i < 8; i++) { woff[i] = s; s += wsum[i]; }
        g_bsum[blockIdx.x] = s;
    }
    __syncthreads();
    int ex = inc - tsum + woff[t >> 5];
    if (base + 0 < NROWS) g_rowptr[base + 0] = ex;
    if (base + 1 < NROWS) g_rowptr[base + 1] = ex + v0;
    if (base + 2 < NROWS) g_rowptr[base + 2] = ex + v0 + v1;
    if (base + 3 < NROWS) g_rowptr[base + 3] = ex + v0 + v1 + v2;
}

__global__ void scan_bsum_k(int nb, const float* __restrict__ logits,
                            const float* __restrict__ alpha) {
    int t = threadIdx.x;
    int v = (t < nb) ? g_bsum[t] : 0;
    int inc = v;
    #pragma unroll
    for (int d = 1; d < 32; d <<= 1) {
        int u = __shfl_up_sync(0xffffffffu, inc, d);
        if ((t & 31) >= d) inc += u;
    }
    __shared__ int ws[8], wo[8];
    if ((t & 31) == 31) ws[t >> 5] = inc;
    __syncthreads();
    if (t == 0) {
        int s = 0;
        for (int i = 0; i < 8; i++) { wo[i] = s; s += ws[i]; }
    }
    __syncthreads();
    if (t < nb) g_bsum[t] = inc - v + wo[t >> 5];
    if (t == 224) {
        float m = logits[0];
        for (int i = 1; i < 16; i++) m = fmaxf(m, logits[i]);
        float e[16], s = 0.f;
        for (int i = 0; i < 16; i++) { e[i] = __expf(logits[i] - m); s += e[i]; }
        float inv = 1.f / s;
        for (int i = 0; i < 16; i++) g_w[i] = e[i] * inv;
        g_w[16] = *alpha;
    }
}

__global__ void scan_add_k() {
    int i = blockIdx.x * blockDim.x + threadIdx.x;
    if (i < NROWS) {
        int v = g_rowptr[i] + g_bsum[i >> 10];
        g_rowptr[i] = v;
        g_cursor[i] = v;
        if (i == 0) g_rowptr[NROWS] = NNZV;
    }
}

__global__ void scatter_k(const void* rowp, const void* colp, const float* __restrict__ v) {
    int i = blockIdx.x * blockDim.x + threadIdx.x;
    if (i < NNZV) {
        int r = edge_at(rowp, i);
        int p = atomicAdd(&g_cursor[r], 1);
        g_edge[p] = make_int2(edge_at(colp, i), __float_as_int(v[i]));
    }
}

// ---------------- full-width fp16 gather: warp-per-row, lane owns 4 channels ----------------
__device__ __forceinline__ float4 spmm_f16(const __half* __restrict__ H,
                                           int beg, int end, int lane) {
    float4 s = make_float4(0.f, 0.f, 0.f, 0.f);
    #pragma unroll 4
    for (int j = beg; j < end; ++j) {
        int2 e = __ldg(g_edge + j);
        float v = __int_as_float(e.y);
        const uint2* p = (const uint2*)(H + (size_t)e.x * HID) + lane;
        uint2 u = __ldg(p);
        __half2 h01 = *(__half2*)&u.x;
        __half2 h23 = *(__half2*)&u.y;
        float2 f01 = __half22float2(h01);
        float2 f23 = __half22float2(h23);
        s.x = fmaf(v, f01.x, s.x); s.y = fmaf(v, f01.y, s.y);
        s.z = fmaf(v, f23.x, s.z); s.w = fmaf(v, f23.y, s.w);
    }
    return s;
}

// block-level max -> ONE atomic per block
__device__ __forceinline__ void block_max(float4 tn, unsigned int* slot) {
    float m = fmaxf(fmaxf(fabsf(tn.x), fabsf(tn.y)), fmaxf(fabsf(tn.z), fabsf(tn.w)));
    #pragma unroll
    for (int d = 16; d > 0; d >>= 1)
        m = fmaxf(m, __shfl_xor_sync(0xffffffffu, m, d));
    __shared__ float wmax[8];
    int wid = threadIdx.x >> 5;
    if ((threadIdx.x & 31) == 0) wmax[wid] = m;
    __syncthreads();
    if (wid == 0) {
        float v = ((threadIdx.x & 31) < 8) ? wmax[threadIdx.x & 31] : 0.f;
        #pragma unroll
        for (int d = 4; d > 0; d >>= 1)
            v = fmaxf(v, __shfl_xor_sync(0xffffffffu, v, d));
        if (threadIdx.x == 0) atomicMax(slot, __float_as_uint(v));
    }
}

__device__ __forceinline__ void mirror_write(__half* Hdst, size_t row, int lane,
                                             float4 tn, unsigned int eS) {
    float inv = __uint_as_float((254u - eS) << 23);   // 2^(127-eS)
    __half2 h01 = __floats2half2_rn(tn.x * inv, tn.y * inv);
    __half2 h23 = __floats2half2_rn(tn.z * inv, tn.w * inv);
    uint2 u;
    u.x = *(unsigned int*)&h01;
    u.y = *(unsigned int*)&h23;
    ((uint2*)(Hdst + row * HID))[lane] = u;
}

// m = 1: fp16 gather of x-mirror (g_Hb); T1 = s - x (x fp32); acc init; mirror T1 -> g_Ha (slot 0); block-max -> slot 1
__global__ void __launch_bounds__(256) cheb_first_k(const float* __restrict__ x) {
    int row = (blockIdx.x * blockDim.x + threadIdx.x) >> 5;
    int lane = threadIdx.x & 31;
    float4 s = spmm_f16(g_Hb, g_rowptr[row], g_rowptr[row + 1], lane);
    unsigned int e0 = slot_sexp(0);
    float scale = __uint_as_float(e0 << 23);
    s.x *= scale; s.y *= scale; s.z *= scale; s.w *= scale;
    size_t off = (size_t)row * HID;
    float4 xr = __ldg((const float4*)(x + off) + lane);
    float w0 = g_w[0], w1 = g_w[1], al = g_w[16];
    float ca = w0 - w1 - al, cb = w1 + 0.5f * al;
    float4 t1, a;
    t1.x = s.x - xr.x; t1.y = s.y - xr.y; t1.z = s.z - xr.z; t1.w = s.w - xr.w;
    a.x = fmaf(ca, xr.x, cb * s.x); a.y = fmaf(ca, xr.y, cb * s.y);
    a.z = fmaf(ca, xr.z, cb * s.z); a.w = fmaf(ca, xr.w, cb * s.w);
    ((float4*)(g_B0 + off))[lane] = t1;
    stcs4((float4*)(g_acc + off) + lane, a);
    mirror_write(g_Ha, row, lane, t1, e0);
    block_max(t1, &g_maxbits2[1 * 8]);
}

// Step m >= 2: fp16 gather of mirror(T_{m-1}); tp from dying mirror(T_{m-2}) (= Hdst, overwritten in place);
// fp32 recurrence; mirror T_m. MODE 0: plain; MODE 1: tri-acc; MODE 2: last. DOMAX: block-max -> slot m.
template<int MODE, bool MIRROR, bool DOMAX>
__global__ void __launch_bounds__(256) cheb_step_t(const float* __restrict__ Tcur,
                                                   float* Tnew,
                                                   float* __restrict__ out,
                                                   const __half* __restrict__ Hsrc,
                                                   __half* Hpd,     // mirror(T_{m-2}) and write target
                                                   int m, int sr, int sp, int sw) {
    int row = (blockIdx.x * blockDim.x + threadIdx.x) >> 5;
    int lane = threadIdx.x & 31;
    float4 s = spmm_f16(Hsrc, g_rowptr[row], g_rowptr[row + 1], lane);
    float scale = __uint_as_float(slot_sexp(sr) << 23);   // 2^(eS-127)
    s.x *= scale; s.y *= scale; s.z *= scale; s.w *= scale;
    size_t off = (size_t)row * HID;
    float4 tc = __ldg((const float4*)(Tcur + off) + lane);
    // tp: decode dying mirror of T_{m-2}
    float4 tp;
    {
        uint2 u = ldcs_u2((const uint2*)(Hpd + off) + lane);
        __half2 h01 = *(__half2*)&u.x;
        __half2 h23 = *(__half2*)&u.y;
        float2 f01 = __half22float2(h01);
        float2 f23 = __half22float2(h23);
        float sc = __uint_as_float(slot_sexp(sp) << 23);
        tp.x = f01.x * sc; tp.y = f01.y * sc; tp.z = f23.x * sc; tp.w = f23.y * sc;
    }
    float4 tn;
    tn.x = 2.f * s.x - 2.f * tc.x - tp.x;
    tn.y = 2.f * s.y - 2.f * tc.y - tp.y;
    tn.z = 2.f * s.z - 2.f * tc.z - tp.z;
    tn.w = 2.f * s.w - 2.f * tc.w - tp.w;
    if (MIRROR) mirror_write(Hpd, row, lane, tn, slot_sexp(sw));
    if (MODE == 0) {
        ((float4*)(Tnew + off))[lane] = tn;
    } else if (MODE == 1) {
        ((float4*)(Tnew + off))[lane] = tn;
        float wa = g_w[m - 2], wb = g_w[m - 1], wc = g_w[m];
        float4 a = ldcs4((const float4*)(g_acc + off) + lane);
        a.x = fmaf(wa, tp.x, fmaf(wb, tc.x, fmaf(wc, tn.x, a.x)));
        a.y = fmaf(wa, tp.y, fmaf(wb, tc.y, fmaf(wc, tn.y, a.y)));
        a.z = fmaf(wa, tp.z, fmaf(wb, tc.z, fmaf(wc, tn.z, a.z)));
        a.w = fmaf(wa, tp.w, fmaf(wb, tc.w, fmaf(wc, tn.w, a.w)));
        stcs4((float4*)(g_acc + off) + lane, a);
    } else {
        float wb = g_w[m - 1], wc = g_w[m];
        float4 a = ldcs4((const float4*)(g_acc + off) + lane);
        float4 o;
        o.x = -fmaf(wb, tc.x, fmaf(wc, tn.x, a.x));
        o.y = -fmaf(wb, tc.y, fmaf(wc, tn.y, a.y));
        o.z = -fmaf(wb, tc.z, fmaf(wc, tn.z, a.z));
        o.w = -fmaf(wb, tc.w, fmaf(wc, tn.w, a.w));
        stcs4((float4*)(out + off) + lane, o);
    }
    if (DOMAX) block_max(tn, &g_maxbits2[m * 8]);
}

// ---------------- host ----------------
extern "C" void kernel_launch(void* const* d_in, const int* in_sizes, int n_in,
                              void* d_out, int out_size) {
    const float* x      = (const float*)d_in[0];
    const float* vals   = (const float*)d_in[1];
    const float* logits = (const float*)d_in[2];
    const float* alpha  = (const float*)d_in[3];
    const void*  erow   = d_in[4];
    const void*  ecol   = d_in[5];
    float* out = (float*)d_out;
    (void)in_sizes; (void)n_in; (void)out_size;

    void *cntp, *b0p, *b1p, *hap, *hbp;
    cudaGetSymbolAddress(&cntp, g_cnt);
    cudaGetSymbolAddress(&b0p, g_B0);
    cudaGetSymbolAddress(&b1p, g_B1);
    cudaGetSymbolAddress(&hap, g_Ha);
    cudaGetSymbolAddress(&hbp, g_Hb);

    cudaMemsetAsync(cntp, 0, NROWS * sizeof(int), 0);
    detect_k<<<1, 128>>>((const unsigned int*)erow);
    maxx_k<<<592, 256>>>((const float4*)x);
    xmirror_k<<<592, 256>>>((const float4*)x);
    hist_k<<<(NNZV + 255) / 256, 256>>>(erow);
    int nb = (NROWS + 1023) / 1024;
    scan_local_k<<<nb, 256>>>();
    scan_bsum_k<<<1, 256>>>(nb, logits, alpha);
    scan_add_k<<<(NROWS + 255) / 256, 256>>>();
    scatter_k<<<(NNZV + 255) / 256, 256>>>(erow, ecol, vals);

    int grid = NROWS * 32 / 256;   // 25000 blocks, exact

    // slotw(m): latest max slot finalized (by kernel boundary) before step m
    auto slotw = [](int m) { return m <= 1 ? 0 : (m <= 4 ? 1 : (m <= 7 ? 4 : (m <= 10 ? 7 : 10))); };
    auto slotw2 = [&](int m) { return m <= 13 ? slotw(m) : 13; };

    cheb_first_k<<<grid, 256>>>(x);   // gathers Hb (x-mirror), writes Ha=mirror(T1), B0, acc

    float* Tcur = (float*)b0p;
    float* Tnew = (float*)b1p;
    const __half* Hsrc = (const __half*)hap;   // mirror(T_{m-1})
    __half* Hpd = (__half*)hbp;                // mirror(T_{m-2}), becomes dst
    for (int m = 2; m <= 15; ++m) {
        int sr = slotw2(m - 1), sp = slotw2(m - 2), sw = slotw2(m);
        if (m == 15)
            cheb_step_t<2, false, false><<<grid, 256>>>(Tcur, Tnew, out, Hsrc, Hpd, m, sr, sp, sw);
        else if (m == 4 || m == 7 || m == 10 || m == 13)
            cheb_step_t<1, true, true><<<grid, 256>>>(Tcur, Tnew, out, Hsrc, Hpd, m, sr, sp, sw);
        else
            cheb_step_t<0, true, false><<<grid, 256>>>(Tcur, Tnew, out, Hsrc, Hpd, m, sr, sp, sw);
        float* tf = Tcur; Tcur = Tnew; Tnew = tf;
        __half* th = (__half*)Hsrc; Hsrc = Hpd; Hpd = th;
    }
}

// round 14
// speedup vs baseline: 3.2927x; 1.1792x over previous
#include <cuda_runtime.h>
#include <cuda_fp16.h>

#define NROWS 200000
#define NNZV  3200000
#define HID   128

// ---------------- static device scratch (no runtime allocation) ----------------
__device__ int   g_cnt[NROWS];
__device__ int   g_rowptr[NROWS + 1];
__device__ int   g_cursor[NROWS];
__device__ int2  g_edge[NNZV];          // packed {col, val_bits}
__device__ float g_acc[NROWS * HID];
__device__ __half g_Ha[NROWS * HID];    // fp16 mirror ping
__device__ __half g_Hb[NROWS * HID];    // fp16 mirror pong (starts as x-mirror)
__device__ unsigned int g_maxbits2[128]; // max|T_m| slots, padded: slot i at [i*8] (32B apart)
__device__ float g_w[20];
__device__ int   g_bsum[256];
__device__ int   g_is64;

// ---------------- cache-hint load/store helpers ----------------
__device__ __forceinline__ float4 ldcs4(const float4* p) {
    float4 r;
    asm volatile("ld.global.cs.v4.f32 {%0,%1,%2,%3}, [%4];"
                 : "=f"(r.x), "=f"(r.y), "=f"(r.z), "=f"(r.w) : "l"(p));
    return r;
}
__device__ __forceinline__ void stcs4(float4* p, float4 v) {
    asm volatile("st.global.cs.v4.f32 [%0], {%1,%2,%3,%4};"
                 :: "l"(p), "f"(v.x), "f"(v.y), "f"(v.z), "f"(v.w));
}
__device__ __forceinline__ uint2 ldcs_u2(const uint2* p) {
    uint2 r;
    asm volatile("ld.global.cs.v2.u32 {%0,%1}, [%2];" : "=r"(r.x), "=r"(r.y) : "l"(p));
    return r;
}

// scale exponent field from a slot: eS = exp(maxbits) + 8
__device__ __forceinline__ unsigned int slot_sexp(int slot) {
    return (g_maxbits2[slot * 8] >> 23) + 8u;
}

__device__ __forceinline__ float4 decode_u2(uint2 u, float sc) {
    __half2 h01 = *(__half2*)&u.x;
    __half2 h23 = *(__half2*)&u.y;
    float2 f01 = __half22float2(h01);
    float2 f23 = __half22float2(h23);
    float4 r;
    r.x = f01.x * sc; r.y = f01.y * sc; r.z = f23.x * sc; r.w = f23.y * sc;
    return r;
}

// ---------------- index dtype detection (int32 vs int64 edges) ----------------
__device__ __forceinline__ int edge_at(const void* p, int i) {
    return g_is64 ? (int)((const long long*)p)[i] : ((const int*)p)[i];
}

__global__ void detect_k(const unsigned int* p) {
    int t = threadIdx.x;
    if (t == 0) {
        int nz = 0;
        for (int i = 1; i < 128; i += 2) nz |= (p[i] != 0u);
        g_is64 = nz ? 0 : 1;
    }
    if (t < 128) g_maxbits2[t] = 0u;
}

// ---------------- max|x| -> slot 0 ----------------
__global__ void maxx_k(const float4* __restrict__ x) {
    int i = blockIdx.x * blockDim.x + threadIdx.x;
    float m = 0.f;
    int n4 = NROWS * HID / 4;
    for (; i < n4; i += gridDim.x * blockDim.x) {
        float4 a = __ldg(x + i);
        m = fmaxf(m, fmaxf(fmaxf(fabsf(a.x), fabsf(a.y)), fmaxf(fabsf(a.z), fabsf(a.w))));
    }
    #pragma unroll
    for (int d = 16; d > 0; d >>= 1)
        m = fmaxf(m, __shfl_xor_sync(0xffffffffu, m, d));
    if ((threadIdx.x & 31) == 0) atomicMax(&g_maxbits2[0], __float_as_uint(m));
}

// x -> fp16 mirror in g_Hb (scale slot 0)
__global__ void xmirror_k(const float4* __restrict__ x) {
    int i = blockIdx.x * blockDim.x + threadIdx.x;
    int n4 = NROWS * HID / 4;
    unsigned int eS = slot_sexp(0);
    float inv = __uint_as_float((254u - eS) << 23);
    for (; i < n4; i += gridDim.x * blockDim.x) {
        float4 a = __ldg(x + i);
        __half2 h01 = __floats2half2_rn(a.x * inv, a.y * inv);
        __half2 h23 = __floats2half2_rn(a.z * inv, a.w * inv);
        uint2 u;
        u.x = *(unsigned int*)&h01;
        u.y = *(unsigned int*)&h23;
        ((uint2*)g_Hb)[i] = u;
    }
}

// ---------------- CSR build ----------------
__global__ void hist_k(const void* rowp) {
    int i = blockIdx.x * blockDim.x + threadIdx.x;
    if (i < NNZV) atomicAdd(&g_cnt[edge_at(rowp, i)], 1);
}

__global__ void scan_local_k() {
    int t = threadIdx.x;
    int base = blockIdx.x * 1024 + t * 4;
    int v0 = (base + 0 < NROWS) ? g_cnt[base + 0] : 0;
    int v1 = (base + 1 < NROWS) ? g_cnt[base + 1] : 0;
    int v2 = (base + 2 < NROWS) ? g_cnt[base + 2] : 0;
    int v3 = (base + 3 < NROWS) ? g_cnt[base + 3] : 0;
    int tsum = v0 + v1 + v2 + v3;
    int inc = tsum;
    #pragma unroll
    for (int d = 1; d < 32; d <<= 1) {
        int u = __shfl_up_sync(0xffffffffu, inc, d);
        if ((t & 31) >= d) inc += u;
    }
    __shared__ int wsum[8], woff[8];
    if ((t & 31) == 31) wsum[t >> 5] = inc;
    __syncthreads();
    if (t == 0) {
        int s = 0;
        for (int i = 0; i < 8; i++) { woff[i] = s; s += wsum[i]; }
        g_bsum[blockIdx.x] = s;
    }
    __syncthreads();
    int ex = inc - tsum + woff[t >> 5];
    if (base + 0 < NROWS) g_rowptr[base + 0] = ex;
    if (base + 1 < NROWS) g_rowptr[base + 1] = ex + v0;
    if (base + 2 < NROWS) g_rowptr[base + 2] = ex + v0 + v1;
    if (base + 3 < NROWS) g_rowptr[base + 3] = ex + v0 + v1 + v2;
}

__global__ void scan_bsum_k(int nb, const float* __restrict__ logits,
                            const float* __restrict__ alpha) {
    int t = threadIdx.x;
    int v = (t < nb) ? g_bsum[t] : 0;
    int inc = v;
    #pragma unroll
    for (int d = 1; d < 32; d <<= 1) {
        int u = __shfl_up_sync(0xffffffffu, inc, d);
        if ((t & 31) >= d) inc += u;
    }
    __shared__ int ws[8], wo[8];
    if ((t & 31) == 31) ws[t >> 5] = inc;
    __syncthreads();
    if (t == 0) {
        int s = 0;
        for (int i = 0; i < 8; i++) { wo[i] = s; s += ws[i]; }
    }
    __syncthreads();
    if (t < nb) g_bsum[t] = inc - v + wo[t >> 5];
    if (t == 224) {
        float m = logits[0];
        for (int i = 1; i < 16; i++) m = fmaxf(m, logits[i]);
        float e[16], s = 0.f;
        for (int i = 0; i < 16; i++) { e[i] = __expf(logits[i] - m); s += e[i]; }
        float inv = 1.f / s;
        for (int i = 0; i < 16; i++) g_w[i] = e[i] * inv;
        g_w[16] = *alpha;
    }
}

__global__ void scan_add_k() {
    int i = blockIdx.x * blockDim.x + threadIdx.x;
    if (i < NROWS) {
        int v = g_rowptr[i] + g_bsum[i >> 10];
        g_rowptr[i] = v;
        g_cursor[i] = v;
        if (i == 0) g_rowptr[NROWS] = NNZV;
    }
}

__global__ void scatter_k(const void* rowp, const void* colp, const float* __restrict__ v) {
    int i = blockIdx.x * blockDim.x + threadIdx.x;
    if (i < NNZV) {
        int r = edge_at(rowp, i);
        int p = atomicAdd(&g_cursor[r], 1);
        g_edge[p] = make_int2(edge_at(colp, i), __float_as_int(v[i]));
    }
}

// ---------------- full-width fp16 gather: warp-per-row, lane owns 4 channels ----------------
__device__ __forceinline__ float4 spmm_f16(const __half* __restrict__ H,
                                           int beg, int end, int lane) {
    float4 s = make_float4(0.f, 0.f, 0.f, 0.f);
    #pragma unroll 4
    for (int j = beg; j < end; ++j) {
        int2 e = __ldg(g_edge + j);
        float v = __int_as_float(e.y);
        const uint2* p = (const uint2*)(H + (size_t)e.x * HID) + lane;
        uint2 u = __ldg(p);
        __half2 h01 = *(__half2*)&u.x;
        __half2 h23 = *(__half2*)&u.y;
        float2 f01 = __half22float2(h01);
        float2 f23 = __half22float2(h23);
        s.x = fmaf(v, f01.x, s.x); s.y = fmaf(v, f01.y, s.y);
        s.z = fmaf(v, f23.x, s.z); s.w = fmaf(v, f23.y, s.w);
    }
    return s;
}

// block-level max -> ONE atomic per block
__device__ __forceinline__ void block_max(float4 tn, unsigned int* slot) {
    float m = fmaxf(fmaxf(fabsf(tn.x), fabsf(tn.y)), fmaxf(fabsf(tn.z), fabsf(tn.w)));
    #pragma unroll
    for (int d = 16; d > 0; d >>= 1)
        m = fmaxf(m, __shfl_xor_sync(0xffffffffu, m, d));
    __shared__ float wmax[8];
    int wid = threadIdx.x >> 5;
    if ((threadIdx.x & 31) == 0) wmax[wid] = m;
    __syncthreads();
    if (wid == 0) {
        float v = ((threadIdx.x & 31) < 8) ? wmax[threadIdx.x & 31] : 0.f;
        #pragma unroll
        for (int d = 4; d > 0; d >>= 1)
            v = fmaxf(v, __shfl_xor_sync(0xffffffffu, v, d));
        if (threadIdx.x == 0) atomicMax(slot, __float_as_uint(v));
    }
}

__device__ __forceinline__ void mirror_write(__half* Hdst, size_t row, int lane,
                                             float4 tn, unsigned int eS) {
    float inv = __uint_as_float((254u - eS) << 23);   // 2^(127-eS)
    __half2 h01 = __floats2half2_rn(tn.x * inv, tn.y * inv);
    __half2 h23 = __floats2half2_rn(tn.z * inv, tn.w * inv);
    uint2 u;
    u.x = *(unsigned int*)&h01;
    u.y = *(unsigned int*)&h23;
    ((uint2*)(Hdst + row * HID))[lane] = u;
}

// m = 1: fp16 gather of x-mirror (g_Hb); T1 = s - x (x fp32); acc init; mirror T1 -> g_Ha (slot 0); block-max -> slot 1
__global__ void __launch_bounds__(256) cheb_first_k(const float* __restrict__ x) {
    int row = (blockIdx.x * blockDim.x + threadIdx.x) >> 5;
    int lane = threadIdx.x & 31;
    float4 s = spmm_f16(g_Hb, g_rowptr[row], g_rowptr[row + 1], lane);
    unsigned int e0 = slot_sexp(0);
    float scale = __uint_as_float(e0 << 23);
    s.x *= scale; s.y *= scale; s.z *= scale; s.w *= scale;
    size_t off = (size_t)row * HID;
    float4 xr = __ldg((const float4*)(x + off) + lane);
    float w0 = g_w[0], w1 = g_w[1], al = g_w[16];
    float ca = w0 - w1 - al, cb = w1 + 0.5f * al;
    float4 t1, a;
    t1.x = s.x - xr.x; t1.y = s.y - xr.y; t1.z = s.z - xr.z; t1.w = s.w - xr.w;
    a.x = fmaf(ca, xr.x, cb * s.x); a.y = fmaf(ca, xr.y, cb * s.y);
    a.z = fmaf(ca, xr.z, cb * s.z); a.w = fmaf(ca, xr.w, cb * s.w);
    stcs4((float4*)(g_acc + off) + lane, a);
    mirror_write(g_Ha, row, lane, t1, e0);
    block_max(t1, &g_maxbits2[1 * 8]);
}

// Step m >= 2: ALL state in fp16 mirrors. Gather + tc from Hsrc; tp from dying Hpd; tn fp32 -> mirror into Hpd.
// MODE 0: plain; MODE 1: tri-acc (acc += wa*tp + wb*tc + wc*tn); MODE 2: last (out = -(acc + wb*tc + wc*tn)).
template<int MODE, bool DOMAX>
__global__ void __launch_bounds__(256) cheb_step_t(float* __restrict__ out,
                                                   const __half* __restrict__ Hsrc,
                                                   __half* Hpd,     // mirror(T_{m-2}) and write target
                                                   int m, int sr, int sp, int sw) {
    int row = (blockIdx.x * blockDim.x + threadIdx.x) >> 5;
    int lane = threadIdx.x & 31;
    float4 s = spmm_f16(Hsrc, g_rowptr[row], g_rowptr[row + 1], lane);
    float scale = __uint_as_float(slot_sexp(sr) << 23);   // 2^(eS-127)
    s.x *= scale; s.y *= scale; s.z *= scale; s.w *= scale;
    size_t off = (size_t)row * HID;
    // tc: decode own row of Hsrc (L2-hot — it is the gather source)
    float4 tc = decode_u2(__ldg((const uint2*)(Hsrc + off) + lane), scale);
    // tp: decode dying mirror of T_{m-2}
    float4 tp = decode_u2(ldcs_u2((const uint2*)(Hpd + off) + lane),
                          __uint_as_float(slot_sexp(sp) << 23));
    float4 tn;
    tn.x = 2.f * s.x - 2.f * tc.x - tp.x;
    tn.y = 2.f * s.y - 2.f * tc.y - tp.y;
    tn.z = 2.f * s.z - 2.f * tc.z - tp.z;
    tn.w = 2.f * s.w - 2.f * tc.w - tp.w;
    if (MODE != 2) mirror_write(Hpd, row, lane, tn, slot_sexp(sw));
    if (MODE == 1) {
        float wa = g_w[m - 2], wb = g_w[m - 1], wc = g_w[m];
        float4 a = ldcs4((const float4*)(g_acc + off) + lane);
        a.x = fmaf(wa, tp.x, fmaf(wb, tc.x, fmaf(wc, tn.x, a.x)));
        a.y = fmaf(wa, tp.y, fmaf(wb, tc.y, fmaf(wc, tn.y, a.y)));
        a.z = fmaf(wa, tp.z, fmaf(wb, tc.z, fmaf(wc, tn.z, a.z)));
        a.w = fmaf(wa, tp.w, fmaf(wb, tc.w, fmaf(wc, tn.w, a.w)));
        stcs4((float4*)(g_acc + off) + lane, a);
    } else if (MODE == 2) {
        float wb = g_w[m - 1], wc = g_w[m];
        float4 a = ldcs4((const float4*)(g_acc + off) + lane);
        float4 o;
        o.x = -fmaf(wb, tc.x, fmaf(wc, tn.x, a.x));
        o.y = -fmaf(wb, tc.y, fmaf(wc, tn.y, a.y));
        o.z = -fmaf(wb, tc.z, fmaf(wc, tn.z, a.z));
        o.w = -fmaf(wb, tc.w, fmaf(wc, tn.w, a.w));
        stcs4((float4*)(out + off) + lane, o);
    }
    if (DOMAX) block_max(tn, &g_maxbits2[m * 8]);
}

// ---------------- host ----------------
extern "C" void kernel_launch(void* const* d_in, const int* in_sizes, int n_in,
                              void* d_out, int out_size) {
    const float* x      = (const float*)d_in[0];
    const float* vals   = (const float*)d_in[1];
    const float* logits = (const float*)d_in[2];
    const float* alpha  = (const float*)d_in[3];
    const void*  erow   = d_in[4];
    const void*  ecol   = d_in[5];
    float* out = (float*)d_out;
    (void)in_sizes; (void)n_in; (void)out_size;

    void *cntp, *hap, *hbp;
    cudaGetSymbolAddress(&cntp, g_cnt);
    cudaGetSymbolAddress(&hap, g_Ha);
    cudaGetSymbolAddress(&hbp, g_Hb);

    cudaMemsetAsync(cntp, 0, NROWS * sizeof(int), 0);
    detect_k<<<1, 128>>>((const unsigned int*)erow);
    maxx_k<<<592, 256>>>((const float4*)x);
    xmirror_k<<<592, 256>>>((const float4*)x);
    hist_k<<<(NNZV + 255) / 256, 256>>>(erow);
    int nb = (NROWS + 1023) / 1024;
    scan_local_k<<<nb, 256>>>();
    scan_bsum_k<<<1, 256>>>(nb, logits, alpha);
    scan_add_k<<<(NROWS + 255) / 256, 256>>>();
    scatter_k<<<(NNZV + 255) / 256, 256>>>(erow, ecol, vals);

    int grid = NROWS * 32 / 256;   // 25000 blocks, exact

    // slotw2(m): latest max slot finalized (by kernel boundary) before step m
    auto slotw = [](int m) { return m <= 1 ? 0 : (m <= 4 ? 1 : (m <= 7 ? 4 : (m <= 10 ? 7 : 10))); };
    auto slotw2 = [&](int m) { return m <= 13 ? slotw(m) : 13; };

    cheb_first_k<<<grid, 256>>>(x);   // gathers Hb (x-mirror), writes Ha=mirror(T1), acc

    const __half* Hsrc = (const __half*)hap;   // mirror(T_{m-1})
    __half* Hpd = (__half*)hbp;                // mirror(T_{m-2}), becomes dst
    for (int m = 2; m <= 15; ++m) {
        int sr = slotw2(m - 1), sp = slotw2(m - 2), sw = slotw2(m);
        if (m == 15)
            cheb_step_t<2, false><<<grid, 256>>>(out, Hsrc, Hpd, m, sr, sp, sw);
        else if (m == 4 || m == 7 || m == 10 || m == 13)
            cheb_step_t<1, true><<<grid, 256>>>(out, Hsrc, Hpd, m, sr, sp, sw);
        else
            cheb_step_t<0, false><<<grid, 256>>>(out, Hsrc, Hpd, m, sr, sp, sw);
        __half* th = (__half*)Hsrc; Hsrc = Hpd; Hpd = th;
    }
}